// round 9
// baseline (speedup 1.0000x reference)
#include <cuda_runtime.h>
#include <cuda_fp16.h>
#include <mma.h>
#include <cstdint>

using namespace nvcuda;

#define Bdim 8
#define Sdim 8192
#define Cdim 512
#define Hdim 128

#define KSPLIT 8
#define SLICE  (Sdim/KSPLIT)   // 1024
#define NCH    32              // logits tiles (256 rows) per batch

// ---------------- scratch (static device globals) ---------------------------
__device__ __half g_xh[(size_t)Bdim * Sdim * Cdim];                     // 67 MB
__device__ __half g_wh[Cdim * Hdim];
__device__ float  g_logits[(size_t)Bdim * Sdim * Hdim];                 // 33.5 MB
__device__ __half g_ah[(size_t)Bdim * Sdim * Hdim];                     // 16.8 MB
__device__ float  g_part_m[Bdim * NCH * Hdim];
__device__ float  g_part_s[Bdim * NCH * Hdim];
__device__ float  g_ctxT_part[(size_t)KSPLIT * Bdim * Cdim * Hdim];     // 16.8 MB
__device__ __half g_cth[Bdim * Cdim * Hdim];                            // 1 MB [b][c][h]

__device__ __forceinline__ void cp16(void* smem_dst, const void* gmem_src) {
    unsigned s = (unsigned)__cvta_generic_to_shared(smem_dst);
    asm volatile("cp.async.cg.shared.global [%0], [%1], 16;\n" ::"r"(s), "l"(gmem_src));
}
#define CP_COMMIT asm volatile("cp.async.commit_group;\n")
#define CP_WAIT2  asm volatile("cp.async.wait_group 2;\n")

typedef wmma::fragment<wmma::accumulator, 16, 16, 16, float> HAcc;
typedef wmma::fragment<wmma::matrix_a, 16, 16, 16, __half, wmma::row_major> HAFragR;
typedef wmma::fragment<wmma::matrix_a, 16, 16, 16, __half, wmma::col_major> HAFragC;
typedef wmma::fragment<wmma::matrix_b, 16, 16, 16, __half, wmma::row_major> HBFragR;
typedef wmma::fragment<wmma::matrix_b, 16, 16, 16, __half, wmma::col_major> HBFragC;

__device__ __forceinline__ uint32_t h2u(__half2 h) {
    uint32_t u;
    *reinterpret_cast<__half2*>(&u) = h;
    return u;
}

// K0: W -> fp16 (RN)
__global__ __launch_bounds__(256) void k_wr(const float* __restrict__ W) {
    int i = blockIdx.x * 256 + threadIdx.x;    // 65536
    g_wh[i] = __float2half_rn(W[i]);
}

// ============================================================================
// K1: logits = x @ W  (bias skipped: softmax over S cancels per-h constants)
// x streams in as fp32; per-chunk convert produces the fp16 MMA tile AND
// writes g_xh. Fused column softmax stats. Block 256x128, warp 64x64, KC=32.
// ============================================================================
__global__ __launch_bounds__(256, 1) void k_logits(const float* __restrict__ x) {
    extern __shared__ char shc[];
    float* shf = reinterpret_cast<float*>(shc);
    __half* shh = reinterpret_cast<__half*>(shc);
    const int tid = threadIdx.x, wid = tid >> 5;
    const int wm = wid >> 1, wn = wid & 1;
    const int m0 = blockIdx.x * 256;

    HAcc c[4][4];
#pragma unroll
    for (int i = 0; i < 4; i++)
#pragma unroll
        for (int j = 0; j < 4; j++) wmma::fill_fragment(c[i][j], 0.0f);

    auto Af = [&](int st) { return shf + st * 9216; };            // fp32 [256][36]
    auto Ws = [&](int st) { return shh + 55296 + st * 4352; };    // fp16 [32][136]
    __half* hbuf = shh + 68352;                                   // fp16 [256][40]

    auto load_tiles = [&](int st, int it) {
        const int kt = it * 32;
        float* a = Af(st);
        __half* w = Ws(st);
#pragma unroll
        for (int i = 0; i < 8; i++) {      // x fp32: 256x32 = 2048 f4
            int idx = tid + i * 256;
            int row = idx >> 3, c4 = idx & 7;
            cp16(a + row * 36 + c4 * 4, x + (size_t)(m0 + row) * Cdim + kt + c4 * 4);
        }
#pragma unroll
        for (int i = 0; i < 2; i++) {      // W fp16: 32x128 halves
            int idx = tid + i * 256;
            int row = idx >> 4, c8 = idx & 15;
            cp16(w + row * 136 + c8 * 8, g_wh + (size_t)(kt + row) * Hdim + c8 * 8);
        }
    };

    const int NIT = 16;
    load_tiles(0, 0); CP_COMMIT;
    load_tiles(1, 1); CP_COMMIT;
    for (int it = 0; it < NIT; ++it) {
        if (it + 2 < NIT) load_tiles((it + 2) % 3, it + 2);
        CP_COMMIT;
        CP_WAIT2;
        __syncthreads();
        const int st = it % 3;
        const int kt = it * 32;
        {
            float* a = Af(st);
#pragma unroll
            for (int i = 0; i < 4; i++) {
                int idx = tid + i * 256;
                int row = idx >> 2, c8 = idx & 3;
                float4 v0 = *reinterpret_cast<float4*>(a + row * 36 + c8 * 8);
                float4 v1 = *reinterpret_cast<float4*>(a + row * 36 + c8 * 8 + 4);
                uint4 pack;
                pack.x = h2u(__floats2half2_rn(v0.x, v0.y));
                pack.y = h2u(__floats2half2_rn(v0.z, v0.w));
                pack.z = h2u(__floats2half2_rn(v1.x, v1.y));
                pack.w = h2u(__floats2half2_rn(v1.z, v1.w));
                *reinterpret_cast<uint4*>(hbuf + row * 40 + c8 * 8) = pack;
                *reinterpret_cast<uint4*>(
                    g_xh + (size_t)(m0 + row) * Cdim + kt + c8 * 8) = pack;
            }
        }
        __syncthreads();
#pragma unroll
        for (int kk = 0; kk < 32; kk += 16) {
            HAFragR a[4];
#pragma unroll
            for (int i = 0; i < 4; i++)
                wmma::load_matrix_sync(a[i], hbuf + (wm * 64 + i * 16) * 40 + kk, 40);
#pragma unroll
            for (int j = 0; j < 4; j++) {
                HBFragR bf;
                wmma::load_matrix_sync(bf, Ws(st) + kk * 136 + wn * 64 + j * 16, 136);
#pragma unroll
                for (int i = 0; i < 4; i++) wmma::mma_sync(c[i][j], a[i], bf, c[i][j]);
            }
        }
        __syncthreads();
    }

    // epilogue: tile -> smem fp32 [256][132], write gmem + column stats
#pragma unroll
    for (int i = 0; i < 4; i++)
#pragma unroll
        for (int j = 0; j < 4; j++)
            wmma::store_matrix_sync(shf + (wm * 64 + i * 16) * 132 + wn * 64 + j * 16,
                                    c[i][j], 132, wmma::mem_row_major);
    __syncthreads();
#pragma unroll
    for (int i = 0; i < 32; i++) {
        int idx = tid + i * 256;
        int row = idx >> 5, c4 = idx & 31;
        float4 v = *reinterpret_cast<float4*>(shf + row * 132 + c4 * 4);
        *reinterpret_cast<float4*>(g_logits + (size_t)(m0 + row) * Hdim + c4 * 4) = v;
    }
    {
        float* pm = shf + 33792;
        float* ps = shf + 34048;
        const int col = tid & 127, half = tid >> 7;
        float m = -1e30f;
#pragma unroll 8
        for (int r = half * 128; r < half * 128 + 128; r++)
            m = fmaxf(m, shf[r * 132 + col]);
        float s = 0.0f;
#pragma unroll 8
        for (int r = half * 128; r < half * 128 + 128; r++)
            s += __expf(shf[r * 132 + col] - m);
        pm[tid] = m; ps[tid] = s;
        __syncthreads();
        if (half == 0) {
            float m1 = pm[col + 128], s1 = ps[col + 128];
            float mn = fmaxf(m, m1);
            float sc = s * __expf(m - mn) + s1 * __expf(m1 - mn);
            const int b = blockIdx.x >> 5, ch = blockIdx.x & 31;
            g_part_m[((size_t)b * NCH + ch) * Hdim + col] = mn;
            g_part_s[((size_t)b * NCH + ch) * Hdim + col] = sc;
        }
    }
}

// ============================================================================
// K2: A = fp16_RN(exp(l - m) * inv). Each block combines the 32 chunk stats
// itself, then converts 64 s-rows x 128 h. grid = 1024 blocks.
// ============================================================================
__global__ __launch_bounds__(256) void k_aconv() {
    __shared__ float sm[128], si[128];
    const int tid = threadIdx.x;
    const int b = blockIdx.x >> 7;
    const int s0 = (blockIdx.x & 127) * 64;

    if (tid < 128) {
        float m = -1e30f, s = 0.0f;
#pragma unroll
        for (int ch = 0; ch < NCH; ch++) {
            float pm = g_part_m[((size_t)b * NCH + ch) * Hdim + tid];
            float ps = g_part_s[((size_t)b * NCH + ch) * Hdim + tid];
            float mn = fmaxf(m, pm);
            s = s * __expf(m - mn) + ps * __expf(pm - mn);
            m = mn;
        }
        sm[tid] = m;
        si[tid] = 1.0f / s;
    }
    __syncthreads();

#pragma unroll
    for (int i = 0; i < 8; i++) {          // 64 rows x 128 h = 2048 f4
        int idx = tid + i * 256;
        int row = idx >> 5, h4 = (idx & 31) * 4;
        size_t g = ((size_t)b * Sdim + s0 + row) * Hdim + h4;
        float4 l = *reinterpret_cast<float4*>(g_logits + g);
        float a0 = __expf(l.x - sm[h4 + 0]) * si[h4 + 0];
        float a1 = __expf(l.y - sm[h4 + 1]) * si[h4 + 1];
        float a2 = __expf(l.z - sm[h4 + 2]) * si[h4 + 2];
        float a3 = __expf(l.w - sm[h4 + 3]) * si[h4 + 3];
        __half2* dst = reinterpret_cast<__half2*>(g_ah + g);
        dst[0] = __floats2half2_rn(a0, a1);
        dst[1] = __floats2half2_rn(a2, a3);
    }
}

// ============================================================================
// K3: ctxT_part[ks][b] = x^T @ A over a 1024-row s-slice. fp16 operands.
// Block 128(c) x 128(h), warp tile 32x64 (8 warps), 2 CTAs/SM, KC=32,
// 3-stage. grid (4 ct, 8 ks, 8 b) = 256 blocks.  (4th launch -> profiled)
// ============================================================================
__global__ __launch_bounds__(256, 2) void k_ctx() {
    extern __shared__ char shc[];
    __half* shh = reinterpret_cast<__half*>(shc);
    // stage = x [32][136] + A [32][136] = 8704 halves
    const int tid = threadIdx.x, wid = tid >> 5;
    const int wm = wid >> 1, wn = wid & 1;   // 4 x 2 positions of 32x64
    const int ct = blockIdx.x, ks = blockIdx.y, b = blockIdx.z;
    const int sbase = ks * SLICE;
    const int c0 = ct * 128;

    HAcc c[2][4];
#pragma unroll
    for (int i = 0; i < 2; i++)
#pragma unroll
        for (int j = 0; j < 4; j++) wmma::fill_fragment(c[i][j], 0.0f);

    auto Xs = [&](int st) { return shh + st * 8704; };            // [32 s][136]
    auto Bs = [&](int st) { return shh + st * 8704 + 4352; };     // [32 s][136]

    auto load_tiles = [&](int st, int it) {
        const int s0 = sbase + it * 32;
        __half* xs = Xs(st);
        __half* bsh = Bs(st);
#pragma unroll
        for (int i = 0; i < 2; i++) {      // x: 32x128 halves = 512 chunks
            int idx = tid + i * 256;
            int row = idx >> 4, c8 = idx & 15;
            cp16(xs + row * 136 + c8 * 8,
                 g_xh + ((size_t)b * Sdim + s0 + row) * Cdim + c0 + c8 * 8);
        }
#pragma unroll
        for (int i = 0; i < 2; i++) {      // A: 32x128 halves = 512 chunks
            int idx = tid + i * 256;
            int row = idx >> 4, c8 = idx & 15;
            cp16(bsh + row * 136 + c8 * 8,
                 g_ah + ((size_t)b * Sdim + s0 + row) * Hdim + c8 * 8);
        }
    };

    const int NIT = SLICE / 32;   // 32
    load_tiles(0, 0); CP_COMMIT;
    load_tiles(1, 1); CP_COMMIT;
    for (int it = 0; it < NIT; ++it) {
        if (it + 2 < NIT) load_tiles((it + 2) % 3, it + 2);
        CP_COMMIT;
        CP_WAIT2;
        __syncthreads();
        const int st = it % 3;
#pragma unroll
        for (int kk = 0; kk < 32; kk += 16) {
            HAFragC a[2];    // M=c from x[s][c] col-major view
#pragma unroll
            for (int i = 0; i < 2; i++)
                wmma::load_matrix_sync(a[i], Xs(st) + kk * 136 + wm * 32 + i * 16, 136);
#pragma unroll
            for (int j = 0; j < 4; j++) {
                HBFragR bf;
                wmma::load_matrix_sync(bf, Bs(st) + kk * 136 + wn * 64 + j * 16, 136);
#pragma unroll
                for (int i = 0; i < 2; i++) wmma::mma_sync(c[i][j], a[i], bf, c[i][j]);
            }
        }
        __syncthreads();
    }
#pragma unroll
    for (int i = 0; i < 2; i++)
#pragma unroll
        for (int j = 0; j < 4; j++)
            wmma::store_matrix_sync(
                g_ctxT_part + (((size_t)ks * Bdim + b) * Cdim + c0 + wm * 32 + i * 16) * Hdim +
                    wn * 64 + j * 16,
                c[i][j], Hdim, wmma::mem_row_major);
}

// K4: deterministic split-K reduce -> g_cth fp16 [b][c][h]
__global__ __launch_bounds__(256) void k_reduce() {
    const size_t f4 = (size_t)blockIdx.x * 256 + threadIdx.x;  // 131072
    float4 s = make_float4(0.f, 0.f, 0.f, 0.f);
#pragma unroll
    for (int p = 0; p < KSPLIT; p++) {
        float4 v = reinterpret_cast<float4*>(
            g_ctxT_part + (size_t)p * Bdim * Cdim * Hdim)[f4];
        s.x += v.x; s.y += v.y; s.z += v.z; s.w += v.w;
    }
    __half2* dst = reinterpret_cast<__half2*>(g_cth) + f4 * 2;
    dst[0] = __floats2half2_rn(s.x, s.y);
    dst[1] = __floats2half2_rn(s.z, s.w);
}

// ============================================================================
// K5: out = A @ ctx. M=8192(s), N=512(c), K=128(h). fp16 operands.
// B = ctx^T consumed col-major. Block 256x128, warp 64x64, KC=32.
// Epilogue staged through smem -> coalesced float4 stores (134 MB write).
// grid (4 ct, 32 mt, 8 b), ct fastest.
// ============================================================================
__global__ __launch_bounds__(256, 1) void k_out(float* __restrict__ out) {
    extern __shared__ char shc[];
    __half* shh = reinterpret_cast<__half*>(shc);
    float* shf = reinterpret_cast<float*>(shc);
    // stage stride = A 256*40 + ctxT 128*40 = 15360 halves
    const int tid = threadIdx.x, wid = tid >> 5;
    const int wm = wid >> 1, wn = wid & 1;
    const int ct = blockIdx.x, mt = blockIdx.y, b = blockIdx.z;
    const int m0 = mt * 256, c0 = ct * 128;

    HAcc c[4][4];
#pragma unroll
    for (int i = 0; i < 4; i++)
#pragma unroll
        for (int j = 0; j < 4; j++) wmma::fill_fragment(c[i][j], 0.0f);

    auto As = [&](int st) { return shh + st * 15360; };           // [256 s][40]
    auto Bs = [&](int st) { return shh + st * 15360 + 10240; };   // [128 c][40]

    auto load_tiles = [&](int st, int it) {
        const int kt = it * 32;
        __half* a = As(st);
        __half* bsh = Bs(st);
#pragma unroll
        for (int i = 0; i < 4; i++) {      // A: 256x32 halves = 1024 chunks
            int idx = tid + i * 256;
            int row = idx >> 2, c8 = idx & 3;
            cp16(a + row * 40 + c8 * 8,
                 g_ah + ((size_t)b * Sdim + m0 + row) * Hdim + kt + c8 * 8);
        }
#pragma unroll
        for (int i = 0; i < 2; i++) {      // ctxT: 128x32 halves = 512 chunks
            int idx = tid + i * 256;
            int row = idx >> 2, c8 = idx & 3;
            cp16(bsh + row * 40 + c8 * 8,
                 g_cth + ((size_t)b * Cdim + c0 + row) * Hdim + kt + c8 * 8);
        }
    };

    const int NIT = 4;
    load_tiles(0, 0); CP_COMMIT;
    load_tiles(1, 1); CP_COMMIT;
    for (int it = 0; it < NIT; ++it) {
        if (it + 2 < NIT) load_tiles((it + 2) % 3, it + 2);
        CP_COMMIT;
        CP_WAIT2;
        __syncthreads();
        const int st = it % 3;
#pragma unroll
        for (int kk = 0; kk < 32; kk += 16) {
            HAFragR a[4];
#pragma unroll
            for (int i = 0; i < 4; i++)
                wmma::load_matrix_sync(a[i], As(st) + (wm * 64 + i * 16) * 40 + kk, 40);
#pragma unroll
            for (int j = 0; j < 4; j++) {
                HBFragC bf;   // B[k=h][n=c] at Bs[c][h] -> col-major, ldm 40
                wmma::load_matrix_sync(bf, Bs(st) + (wn * 64 + j * 16) * 40 + kk, 40);
#pragma unroll
                for (int i = 0; i < 4; i++) wmma::mma_sync(c[i][j], a[i], bf, c[i][j]);
            }
        }
        __syncthreads();
    }

    // epilogue: two 128-row passes through smem, coalesced float4 stores
#pragma unroll
    for (int p = 0; p < 2; p++) {
        __syncthreads();
        if ((wm >> 1) == p) {
#pragma unroll
            for (int i = 0; i < 4; i++)
#pragma unroll
                for (int j = 0; j < 4; j++)
                    wmma::store_matrix_sync(
                        shf + ((wm & 1) * 64 + i * 16) * 132 + wn * 64 + j * 16,
                        c[i][j], 132, wmma::mem_row_major);
        }
        __syncthreads();
        const int mb = m0 + p * 128;
#pragma unroll
        for (int i = 0; i < 16; i++) {       // 128 rows x 32 f4 = 4096
            int idx = tid + i * 256;
            int row = idx >> 5, c4 = idx & 31;
            float4 v = *reinterpret_cast<float4*>(shf + row * 132 + c4 * 4);
            *reinterpret_cast<float4*>(
                out + ((size_t)b * Sdim + mb + row) * Cdim + c0 + c4 * 4) = v;
        }
    }
}

// ============================================================================
extern "C" void kernel_launch(void* const* d_in, const int* in_sizes, int n_in,
                              void* d_out, int out_size) {
    const float* x = (const float*)d_in[0];  // [B, S, C]
    const float* W = (const float*)d_in[1];  // [C, H]
    // d_in[2] (bias) cancels in softmax over S — skipped, exact.
    float* out = (float*)d_out;

    const size_t sh_logits = 157184;   // fp32 A stages + fp16 W stages + fp16 buf
    const size_t sh_ctx    = 52224;    // 3 x 8704 halves
    const size_t sh_out    = 92160;    // pipeline (>=67584 epilogue tile)
    cudaFuncSetAttribute(k_logits, cudaFuncAttributeMaxDynamicSharedMemorySize,
                         (int)sh_logits);
    cudaFuncSetAttribute(k_ctx, cudaFuncAttributeMaxDynamicSharedMemorySize,
                         (int)sh_ctx);
    cudaFuncSetAttribute(k_out, cudaFuncAttributeMaxDynamicSharedMemorySize,
                         (int)sh_out);

    k_wr<<<Cdim * Hdim / 256, 256>>>(W);
    k_logits<<<(Bdim * Sdim) / 256, 256, sh_logits>>>(x);
    k_aconv<<<1024, 256>>>();
    k_ctx<<<dim3(Cdim / 128, KSPLIT, Bdim), 256, sh_ctx>>>();   // 4th launch
    k_reduce<<<512, 256>>>();
    k_out<<<dim3(Cdim / 128, Sdim / 256, Bdim), 256, sh_out>>>(out);
}

// round 10
// speedup vs baseline: 1.5299x; 1.5299x over previous
#include <cuda_runtime.h>
#include <cuda_fp16.h>
#include <mma.h>
#include <cstdint>

using namespace nvcuda;

#define Bdim 8
#define Sdim 8192
#define Cdim 512
#define Hdim 128

#define KSPLIT 8
#define SLICE  (Sdim/KSPLIT)   // 1024
#define NCH    64              // logits tiles (128 rows) per batch

// ---------------- scratch (static device globals) ---------------------------
__device__ __half g_xh[(size_t)Bdim * Sdim * Cdim];                     // 67 MB
__device__ __half g_wh[Cdim * Hdim];
__device__ float  g_logits[(size_t)Bdim * Sdim * Hdim];                 // 33.5 MB
__device__ __half g_ah[(size_t)Bdim * Sdim * Hdim];                     // 16.8 MB
__device__ float  g_part_m[Bdim * NCH * Hdim];
__device__ float  g_part_s[Bdim * NCH * Hdim];
__device__ float  g_ctxT_part[(size_t)KSPLIT * Bdim * Cdim * Hdim];     // 16.8 MB
__device__ __half g_cth[Bdim * Cdim * Hdim];                            // 1 MB [b][c][h]

__device__ __forceinline__ void cp16(void* smem_dst, const void* gmem_src) {
    unsigned s = (unsigned)__cvta_generic_to_shared(smem_dst);
    asm volatile("cp.async.cg.shared.global [%0], [%1], 16;\n" ::"r"(s), "l"(gmem_src));
}
#define CP_COMMIT asm volatile("cp.async.commit_group;\n")
#define CP_WAIT2  asm volatile("cp.async.wait_group 2;\n")

typedef wmma::fragment<wmma::accumulator, 16, 16, 16, float> HAcc;
typedef wmma::fragment<wmma::matrix_a, 16, 16, 16, __half, wmma::row_major> HAFragR;
typedef wmma::fragment<wmma::matrix_a, 16, 16, 16, __half, wmma::col_major> HAFragC;
typedef wmma::fragment<wmma::matrix_b, 16, 16, 16, __half, wmma::row_major> HBFragR;
typedef wmma::fragment<wmma::matrix_b, 16, 16, 16, __half, wmma::col_major> HBFragC;

__device__ __forceinline__ uint32_t h2u(__half2 h) {
    uint32_t u;
    *reinterpret_cast<__half2*>(&u) = h;
    return u;
}

// K0: W -> fp16 (RN)
__global__ __launch_bounds__(256) void k_wr(const float* __restrict__ W) {
    int i = blockIdx.x * 256 + threadIdx.x;    // 65536
    g_wh[i] = __float2half_rn(W[i]);
}

// ============================================================================
// K1: logits = x @ W  (bias skipped: softmax over S cancels per-h constants)
// x streams in as fp32; per-chunk convert produces the fp16 MMA tile AND
// writes g_xh. Fused per-128-row-tile column softmax stats.
// Block 128x128, warp tile 32x64 (8 warps), 2 CTAs/SM, KC=32, 3-stage.
// ============================================================================
__global__ __launch_bounds__(256, 2) void k_logits(const float* __restrict__ x) {
    extern __shared__ char shc[];
    float* shf = reinterpret_cast<float*>(shc);
    __half* shh = reinterpret_cast<__half*>(shc);
    // halves layout: fp32 A stages [3][128][36] (= shf + st*4608 floats),
    // W fp16 stages [3][32][136] @27648h, hbuf [128][40] @40704h
    const int tid = threadIdx.x, wid = tid >> 5;
    const int wm = wid >> 1, wn = wid & 1;     // 4 x 2 positions of 32x64
    const int m0 = blockIdx.x * 128;

    HAcc c[2][4];
#pragma unroll
    for (int i = 0; i < 2; i++)
#pragma unroll
        for (int j = 0; j < 4; j++) wmma::fill_fragment(c[i][j], 0.0f);

    auto Af = [&](int st) { return shf + st * 4608; };            // fp32 [128][36]
    auto Ws = [&](int st) { return shh + 27648 + st * 4352; };    // fp16 [32][136]
    __half* hbuf = shh + 40704;                                   // fp16 [128][40]

    auto load_tiles = [&](int st, int it) {
        const int kt = it * 32;
        float* a = Af(st);
        __half* w = Ws(st);
#pragma unroll
        for (int i = 0; i < 4; i++) {      // x fp32: 128x32 = 1024 f4
            int idx = tid + i * 256;
            int row = idx >> 3, c4 = idx & 7;
            cp16(a + row * 36 + c4 * 4, x + (size_t)(m0 + row) * Cdim + kt + c4 * 4);
        }
#pragma unroll
        for (int i = 0; i < 2; i++) {      // W fp16: 32x128 halves
            int idx = tid + i * 256;
            int row = idx >> 4, c8 = idx & 15;
            cp16(w + row * 136 + c8 * 8, g_wh + (size_t)(kt + row) * Hdim + c8 * 8);
        }
    };

    const int NIT = 16;
    load_tiles(0, 0); CP_COMMIT;
    load_tiles(1, 1); CP_COMMIT;
    for (int it = 0; it < NIT; ++it) {
        if (it + 2 < NIT) load_tiles((it + 2) % 3, it + 2);
        CP_COMMIT;
        CP_WAIT2;
        __syncthreads();
        const int st = it % 3;
        const int kt = it * 32;
        // convert fp32 tile -> fp16 buf + write g_xh (16B pieces, coalesced)
        {
            float* a = Af(st);
#pragma unroll
            for (int i = 0; i < 2; i++) {   // 128 rows x 4 uint4 = 512
                int idx = tid + i * 256;
                int row = idx >> 2, c8 = idx & 3;
                float4 v0 = *reinterpret_cast<float4*>(a + row * 36 + c8 * 8);
                float4 v1 = *reinterpret_cast<float4*>(a + row * 36 + c8 * 8 + 4);
                uint4 pack;
                pack.x = h2u(__floats2half2_rn(v0.x, v0.y));
                pack.y = h2u(__floats2half2_rn(v0.z, v0.w));
                pack.z = h2u(__floats2half2_rn(v1.x, v1.y));
                pack.w = h2u(__floats2half2_rn(v1.z, v1.w));
                *reinterpret_cast<uint4*>(hbuf + row * 40 + c8 * 8) = pack;
                *reinterpret_cast<uint4*>(
                    g_xh + (size_t)(m0 + row) * Cdim + kt + c8 * 8) = pack;
            }
        }
        __syncthreads();
#pragma unroll
        for (int kk = 0; kk < 32; kk += 16) {
            HAFragR a[2];
#pragma unroll
            for (int i = 0; i < 2; i++)
                wmma::load_matrix_sync(a[i], hbuf + (wm * 32 + i * 16) * 40 + kk, 40);
#pragma unroll
            for (int j = 0; j < 4; j++) {
                HBFragR bf;
                wmma::load_matrix_sync(bf, Ws(st) + kk * 136 + wn * 64 + j * 16, 136);
#pragma unroll
                for (int i = 0; i < 2; i++) wmma::mma_sync(c[i][j], a[i], bf, c[i][j]);
            }
        }
        __syncthreads();
    }

    // epilogue: tile -> smem fp32 [128][132], write gmem + column stats
#pragma unroll
    for (int i = 0; i < 2; i++)
#pragma unroll
        for (int j = 0; j < 4; j++)
            wmma::store_matrix_sync(shf + (wm * 32 + i * 16) * 132 + wn * 64 + j * 16,
                                    c[i][j], 132, wmma::mem_row_major);
    __syncthreads();
#pragma unroll
    for (int i = 0; i < 16; i++) {         // 128 rows x 32 f4 = 4096
        int idx = tid + i * 256;
        int row = idx >> 5, c4 = idx & 31;
        float4 v = *reinterpret_cast<float4*>(shf + row * 132 + c4 * 4);
        *reinterpret_cast<float4*>(g_logits + (size_t)(m0 + row) * Hdim + c4 * 4) = v;
    }
    {
        float* pm = shf + 16896;
        float* ps = shf + 17152;
        const int col = tid & 127, half = tid >> 7;
        float m = -1e30f;
#pragma unroll 8
        for (int r = half * 64; r < half * 64 + 64; r++)
            m = fmaxf(m, shf[r * 132 + col]);
        float s = 0.0f;
#pragma unroll 8
        for (int r = half * 64; r < half * 64 + 64; r++)
            s += __expf(shf[r * 132 + col] - m);
        pm[tid] = m; ps[tid] = s;
        __syncthreads();
        if (half == 0) {
            float m1 = pm[col + 128], s1 = ps[col + 128];
            float mn = fmaxf(m, m1);
            float sc = s * __expf(m - mn) + s1 * __expf(m1 - mn);
            const int b = blockIdx.x >> 6, ch = blockIdx.x & 63;
            g_part_m[((size_t)b * NCH + ch) * Hdim + col] = mn;
            g_part_s[((size_t)b * NCH + ch) * Hdim + col] = sc;
        }
    }
}

// ============================================================================
// K2: A = fp16_RN(exp(l - m) * inv). Each block combines the NCH chunk stats
// itself, then converts 64 s-rows x 128 h. grid = 1024 blocks.
// ============================================================================
__global__ __launch_bounds__(256) void k_aconv() {
    __shared__ float sm[128], si[128];
    const int tid = threadIdx.x;
    const int b = blockIdx.x >> 7;
    const int s0 = (blockIdx.x & 127) * 64;

    if (tid < 128) {
        float m = -1e30f, s = 0.0f;
#pragma unroll
        for (int ch = 0; ch < NCH; ch++) {
            float pm = g_part_m[((size_t)b * NCH + ch) * Hdim + tid];
            float ps = g_part_s[((size_t)b * NCH + ch) * Hdim + tid];
            float mn = fmaxf(m, pm);
            s = s * __expf(m - mn) + ps * __expf(pm - mn);
            m = mn;
        }
        sm[tid] = m;
        si[tid] = 1.0f / s;
    }
    __syncthreads();

#pragma unroll
    for (int i = 0; i < 8; i++) {          // 64 rows x 128 h = 2048 f4
        int idx = tid + i * 256;
        int row = idx >> 5, h4 = (idx & 31) * 4;
        size_t g = ((size_t)b * Sdim + s0 + row) * Hdim + h4;
        float4 l = *reinterpret_cast<float4*>(g_logits + g);
        float a0 = __expf(l.x - sm[h4 + 0]) * si[h4 + 0];
        float a1 = __expf(l.y - sm[h4 + 1]) * si[h4 + 1];
        float a2 = __expf(l.z - sm[h4 + 2]) * si[h4 + 2];
        float a3 = __expf(l.w - sm[h4 + 3]) * si[h4 + 3];
        __half2* dst = reinterpret_cast<__half2*>(g_ah + g);
        dst[0] = __floats2half2_rn(a0, a1);
        dst[1] = __floats2half2_rn(a2, a3);
    }
}

// ============================================================================
// K3: ctxT_part[ks][b] = x^T @ A over a 1024-row s-slice. fp16 operands.
// Output ctx^T tile [c=256][h=128]. Warp 64x64, KC=32, 3-stage.
// grid (2 ct, 8 ks, 8 b) = 128 blocks.  (4th launch -> profiled)
// ============================================================================
__global__ __launch_bounds__(256, 1) void k_ctx() {
    extern __shared__ char shc[];
    __half* shh = reinterpret_cast<__half*>(shc);
    // stage stride = x 32*264 + A 32*136 = 12800 halves
    const int tid = threadIdx.x, wid = tid >> 5;
    const int wm = wid >> 1, wn = wid & 1;
    const int ct = blockIdx.x, ks = blockIdx.y, b = blockIdx.z;
    const int sbase = ks * SLICE;
    const int c0 = ct * 256;

    HAcc c[4][4];
#pragma unroll
    for (int i = 0; i < 4; i++)
#pragma unroll
        for (int j = 0; j < 4; j++) wmma::fill_fragment(c[i][j], 0.0f);

    auto Xs = [&](int st) { return shh + st * 12800; };           // [32 s][264]
    auto Bs = [&](int st) { return shh + st * 12800 + 8448; };    // [32 s][136]

    auto load_tiles = [&](int st, int it) {
        const int s0 = sbase + it * 32;
        __half* xs = Xs(st);
        __half* bsh = Bs(st);
#pragma unroll
        for (int i = 0; i < 4; i++) {      // x: 32x256 halves = 1024 chunks
            int idx = tid + i * 256;
            int row = idx >> 5, c8 = idx & 31;
            cp16(xs + row * 264 + c8 * 8,
                 g_xh + ((size_t)b * Sdim + s0 + row) * Cdim + c0 + c8 * 8);
        }
#pragma unroll
        for (int i = 0; i < 2; i++) {      // A: 32x128 halves = 512 chunks
            int idx = tid + i * 256;
            int row = idx >> 4, c8 = idx & 15;
            cp16(bsh + row * 136 + c8 * 8,
                 g_ah + ((size_t)b * Sdim + s0 + row) * Hdim + c8 * 8);
        }
    };

    const int NIT = SLICE / 32;   // 32
    load_tiles(0, 0); CP_COMMIT;
    load_tiles(1, 1); CP_COMMIT;
    for (int it = 0; it < NIT; ++it) {
        if (it + 2 < NIT) load_tiles((it + 2) % 3, it + 2);
        CP_COMMIT;
        CP_WAIT2;
        __syncthreads();
        const int st = it % 3;
#pragma unroll
        for (int kk = 0; kk < 32; kk += 16) {
            HAFragC a[4];    // M=c from x[s][c] col-major view
#pragma unroll
            for (int i = 0; i < 4; i++)
                wmma::load_matrix_sync(a[i], Xs(st) + kk * 264 + wm * 64 + i * 16, 264);
#pragma unroll
            for (int j = 0; j < 4; j++) {
                HBFragR bf;
                wmma::load_matrix_sync(bf, Bs(st) + kk * 136 + wn * 64 + j * 16, 136);
#pragma unroll
                for (int i = 0; i < 4; i++) wmma::mma_sync(c[i][j], a[i], bf, c[i][j]);
            }
        }
        __syncthreads();
    }
#pragma unroll
    for (int i = 0; i < 4; i++)
#pragma unroll
        for (int j = 0; j < 4; j++)
            wmma::store_matrix_sync(
                g_ctxT_part + (((size_t)ks * Bdim + b) * Cdim + c0 + wm * 64 + i * 16) * Hdim +
                    wn * 64 + j * 16,
                c[i][j], Hdim, wmma::mem_row_major);
}

// K4: deterministic split-K reduce -> g_cth fp16 [b][c][h]
__global__ __launch_bounds__(256) void k_reduce() {
    const size_t f4 = (size_t)blockIdx.x * 256 + threadIdx.x;  // 131072
    float4 s = make_float4(0.f, 0.f, 0.f, 0.f);
#pragma unroll
    for (int p = 0; p < KSPLIT; p++) {
        float4 v = reinterpret_cast<float4*>(
            g_ctxT_part + (size_t)p * Bdim * Cdim * Hdim)[f4];
        s.x += v.x; s.y += v.y; s.z += v.z; s.w += v.w;
    }
    __half2* dst = reinterpret_cast<__half2*>(g_cth) + f4 * 2;
    dst[0] = __floats2half2_rn(s.x, s.y);
    dst[1] = __floats2half2_rn(s.z, s.w);
}

// ============================================================================
// K5: out = A @ ctx. M=8192(s), N=512(c), K=128(h). fp16 operands.
// B = ctx^T fp16 consumed col-major. Block 256x128, warp 64x64, KC=32.
// grid (4 ct, 32 mt, 8 b), ct fastest.  (R8 epilogue: direct stores)
// ============================================================================
__global__ __launch_bounds__(256, 1) void k_out(float* __restrict__ out) {
    extern __shared__ char shc[];
    __half* shh = reinterpret_cast<__half*>(shc);
    // stage stride = A 256*40 + ctxT 128*40 = 15360 halves
    const int tid = threadIdx.x, wid = tid >> 5;
    const int wm = wid >> 1, wn = wid & 1;
    const int ct = blockIdx.x, mt = blockIdx.y, b = blockIdx.z;
    const int m0 = mt * 256, c0 = ct * 128;

    HAcc c[4][4];
#pragma unroll
    for (int i = 0; i < 4; i++)
#pragma unroll
        for (int j = 0; j < 4; j++) wmma::fill_fragment(c[i][j], 0.0f);

    auto As = [&](int st) { return shh + st * 15360; };           // [256 s][40]
    auto Bs = [&](int st) { return shh + st * 15360 + 10240; };   // [128 c][40]

    auto load_tiles = [&](int st, int it) {
        const int kt = it * 32;
        __half* a = As(st);
        __half* bsh = Bs(st);
#pragma unroll
        for (int i = 0; i < 4; i++) {      // A: 256x32 halves = 1024 chunks
            int idx = tid + i * 256;
            int row = idx >> 2, c8 = idx & 3;
            cp16(a + row * 40 + c8 * 8,
                 g_ah + ((size_t)b * Sdim + m0 + row) * Hdim + kt + c8 * 8);
        }
#pragma unroll
        for (int i = 0; i < 2; i++) {      // ctxT: 128x32 halves = 512 chunks
            int idx = tid + i * 256;
            int row = idx >> 2, c8 = idx & 3;
            cp16(bsh + row * 40 + c8 * 8,
                 g_cth + ((size_t)b * Cdim + c0 + row) * Hdim + kt + c8 * 8);
        }
    };

    const int NIT = 4;
    load_tiles(0, 0); CP_COMMIT;
    load_tiles(1, 1); CP_COMMIT;
    for (int it = 0; it < NIT; ++it) {
        if (it + 2 < NIT) load_tiles((it + 2) % 3, it + 2);
        CP_COMMIT;
        CP_WAIT2;
        __syncthreads();
        const int st = it % 3;
#pragma unroll
        for (int kk = 0; kk < 32; kk += 16) {
            HAFragR a[4];
#pragma unroll
            for (int i = 0; i < 4; i++)
                wmma::load_matrix_sync(a[i], As(st) + (wm * 64 + i * 16) * 40 + kk, 40);
#pragma unroll
            for (int j = 0; j < 4; j++) {
                HBFragC bf;   // B[k=h][n=c] at Bs[c][h] -> col-major, ldm 40
                wmma::load_matrix_sync(bf, Bs(st) + (wn * 64 + j * 16) * 40 + kk, 40);
#pragma unroll
                for (int i = 0; i < 4; i++) wmma::mma_sync(c[i][j], a[i], bf, c[i][j]);
            }
        }
        __syncthreads();
    }
#pragma unroll
    for (int i = 0; i < 4; i++)
#pragma unroll
        for (int j = 0; j < 4; j++)
            wmma::store_matrix_sync(
                out + ((size_t)b * Sdim + m0 + wm * 64 + i * 16) * Cdim + c0 +
                    wn * 64 + j * 16,
                c[i][j], Cdim, wmma::mem_row_major);
}

// ============================================================================
extern "C" void kernel_launch(void* const* d_in, const int* in_sizes, int n_in,
                              void* d_out, int out_size) {
    const float* x = (const float*)d_in[0];  // [B, S, C]
    const float* W = (const float*)d_in[1];  // [C, H]
    // d_in[2] (bias) cancels in softmax over S — skipped, exact.
    float* out = (float*)d_out;

    const size_t sh_logits = 91648;    // 3-stage fp32 A + fp16 W + hbuf (2 CTAs/SM)
    const size_t sh_ctx    = 76800;
    const size_t sh_out    = 92160;
    cudaFuncSetAttribute(k_logits, cudaFuncAttributeMaxDynamicSharedMemorySize,
                         (int)sh_logits);
    cudaFuncSetAttribute(k_ctx, cudaFuncAttributeMaxDynamicSharedMemorySize,
                         (int)sh_ctx);
    cudaFuncSetAttribute(k_out, cudaFuncAttributeMaxDynamicSharedMemorySize,
                         (int)sh_out);

    k_wr<<<Cdim * Hdim / 256, 256>>>(W);
    k_logits<<<(Bdim * Sdim) / 128, 256, sh_logits>>>(x);
    k_aconv<<<1024, 256>>>();
    k_ctx<<<dim3(Cdim / 256, KSPLIT, Bdim), 256, sh_ctx>>>();   // 4th launch
    k_reduce<<<512, 256>>>();
    k_out<<<dim3(Cdim / 128, Sdim / 256, Bdim), 256, sh_out>>>(out);
}